// round 3
// baseline (speedup 1.0000x reference)
#include <cuda_runtime.h>
#include <cstdint>

// Problem constants (fixed shapes for this dataset)
#define DD        256      // feature dim
#define G_LD      1024     // packed gate GEMM output width (4 gates x 256)
#define GK        512      // packed gate GEMM K (agg 256 | memory 256)
#define NODES_MAX 100000

#define BM 128
#define BN 128
#define BK 16
#define PAD_A 132          // smem A pitch (float4-aligned, reduces STS conflicts)

// Static scratch (no allocations allowed)
__device__ float g_G[(size_t)NODES_MAX * G_LD];   // gate preacts: [N][r|z|xn|hn]
__device__ float g_Bpack[GK * G_LD];              // packed [W_gru;U_gru] gate matrix
__device__ int   g_counts[NODES_MAX];

static inline int cdiv(int a, int b) { return (a + b - 1) / b; }

__device__ __forceinline__ void red_add_v4(float* p, float a, float b, float c, float d) {
    asm volatile("red.global.add.v4.f32 [%0], {%1, %2, %3, %4};"
                 :: "l"(p), "f"(a), "f"(b), "f"(c), "f"(d) : "memory");
}

__device__ __forceinline__ float sigmoidf_(float x) {
    return 1.f / (1.f + expf(-x));
}

// ---------------------------------------------------------------------------
// K0: zero agg (= d_out) and counts
// ---------------------------------------------------------------------------
__global__ void zero_kernel(float4* __restrict__ out4, int n4, int N) {
    int i = blockIdx.x * blockDim.x + threadIdx.x;
    if (i < n4) out4[i] = make_float4(0.f, 0.f, 0.f, 0.f);
    if (i < N)  g_counts[i] = 0;
}

// ---------------------------------------------------------------------------
// K1: per-node message counts (both edge stores)
// ---------------------------------------------------------------------------
__global__ void count_kernel(const int* __restrict__ s_src,
                             const int* __restrict__ d_src, int M) {
    int e = blockIdx.x * blockDim.x + threadIdx.x;
    if (e < 2 * M) {
        int node = (e < M) ? s_src[e] : d_src[e - M];
        atomicAdd(&g_counts[node], 1);
    }
}

// ---------------------------------------------------------------------------
// K2: pack B for the fused gate GEMM.
//   col j = gate*256 + c, gates: 0 -> r (W|U), 1 -> z (W|U), 2 -> xn (W|0), 3 -> hn (0|U)
// ---------------------------------------------------------------------------
__global__ void pack_kernel(const float* __restrict__ Wg, const float* __restrict__ Ug) {
    int idx = blockIdx.x * blockDim.x + threadIdx.x;
    if (idx >= GK * G_LD) return;
    int k = idx >> 10, j = idx & (G_LD - 1);
    int gate = j >> 8, col = j & 255;
    float v = 0.f;
    if (gate == 0)      v = (k < 256) ? Wg[k * 768 + col]       : Ug[(k - 256) * 768 + col];
    else if (gate == 1) v = (k < 256) ? Wg[k * 768 + 256 + col] : Ug[(k - 256) * 768 + 256 + col];
    else if (gate == 2) v = (k < 256) ? Wg[k * 768 + 512 + col] : 0.f;
    else                v = (k < 256) ? 0.f                      : Ug[(k - 256) * 768 + 512 + col];
    g_Bpack[idx] = v;
}

// Shared tile staging macro (locals pa0..pb1, ak, ar, bk, bc must exist)
#define STORE_AB(nb) do {                                                                     \
    As[nb][ak+0][ar]    = pa0.x; As[nb][ak+1][ar]    = pa0.y;                                 \
    As[nb][ak+2][ar]    = pa0.z; As[nb][ak+3][ar]    = pa0.w;                                 \
    As[nb][ak+0][64+ar] = pa1.x; As[nb][ak+1][64+ar] = pa1.y;                                 \
    As[nb][ak+2][64+ar] = pa1.z; As[nb][ak+3][64+ar] = pa1.w;                                 \
    *(float4*)&Bs[nb][bk][bc]     = pb0;                                                      \
    *(float4*)&Bs[nb][8+bk][bc]   = pb1;                                                      \
} while (0)

// ---------------------------------------------------------------------------
// K3: message GEMM (raw[M,K] @ W[K,256] + b) fused with scatter-add into agg
// ---------------------------------------------------------------------------
__global__ __launch_bounds__(256, 2)
void msg_gemm_scatter(const float* __restrict__ A, const float* __restrict__ B,
                      const float* __restrict__ bias, const int* __restrict__ src,
                      float* __restrict__ agg, int M, int K)
{
    __shared__ __align__(16) float As[2][BK][PAD_A];
    __shared__ __align__(16) float Bs[2][BK][BN];
    const int tid = threadIdx.x;
    const int rowBase = blockIdx.x * BM;
    const int colBase = blockIdx.y * BN;

    const int ar = tid >> 2;            // 0..63
    const int ak = (tid & 3) << 2;      // 0,4,8,12
    const int bk = tid >> 5;            // 0..7
    const int bc = (tid & 31) << 2;     // 0..124
    const int trow = (tid >> 4) << 2;   // 0..60
    const int tcol = (tid & 15) << 2;   // 0..60

    const int r0 = rowBase + ar, r1 = rowBase + 64 + ar;
    const bool ok0 = r0 < M, ok1 = r1 < M;
    const float* A0 = A + (size_t)r0 * K + ak;
    const float* A1 = A + (size_t)r1 * K + ak;
    const float4 z4 = make_float4(0.f, 0.f, 0.f, 0.f);

    float acc[8][8];
#pragma unroll
    for (int i = 0; i < 8; i++)
#pragma unroll
        for (int j = 0; j < 8; j++) acc[i][j] = 0.f;

    float4 pa0, pa1, pb0, pb1;
    pa0 = ok0 ? *(const float4*)(A0) : z4;
    pa1 = ok1 ? *(const float4*)(A1) : z4;
    pb0 = *(const float4*)(B + (size_t)(bk)     * DD + colBase + bc);
    pb1 = *(const float4*)(B + (size_t)(8 + bk) * DD + colBase + bc);
    STORE_AB(0);
    __syncthreads();

    const int nk = K / BK;
    for (int kt = 0; kt < nk; kt++) {
        const int buf = kt & 1;
        if (kt + 1 < nk) {
            const int k0 = (kt + 1) * BK;
            pa0 = ok0 ? *(const float4*)(A0 + k0) : z4;
            pa1 = ok1 ? *(const float4*)(A1 + k0) : z4;
            pb0 = *(const float4*)(B + (size_t)(k0 + bk)     * DD + colBase + bc);
            pb1 = *(const float4*)(B + (size_t)(k0 + 8 + bk) * DD + colBase + bc);
        }
#pragma unroll
        for (int kk = 0; kk < BK; kk++) {
            float4 a0 = *(const float4*)&As[buf][kk][trow];
            float4 a1 = *(const float4*)&As[buf][kk][64 + trow];
            float4 b0 = *(const float4*)&Bs[buf][kk][tcol];
            float4 b1 = *(const float4*)&Bs[buf][kk][64 + tcol];
            float av[8] = {a0.x, a0.y, a0.z, a0.w, a1.x, a1.y, a1.z, a1.w};
            float bv[8] = {b0.x, b0.y, b0.z, b0.w, b1.x, b1.y, b1.z, b1.w};
#pragma unroll
            for (int i = 0; i < 8; i++)
#pragma unroll
                for (int j = 0; j < 8; j++)
                    acc[i][j] = fmaf(av[i], bv[j], acc[i][j]);
        }
        if (kt + 1 < nk) { const int nb = buf ^ 1; STORE_AB(nb); }
        __syncthreads();
    }

    const float4 bi0 = *(const float4*)(bias + colBase + tcol);
    const float4 bi1 = *(const float4*)(bias + colBase + 64 + tcol);
#pragma unroll
    for (int ii = 0; ii < 8; ii++) {
        const int r = rowBase + ((ii < 4) ? (trow + ii) : (64 + trow + (ii - 4)));
        if (r < M) {
            const int node = __ldg(&src[r]);
            float* p = agg + (size_t)node * DD + colBase + tcol;
            red_add_v4(p,      acc[ii][0] + bi0.x, acc[ii][1] + bi0.y,
                               acc[ii][2] + bi0.z, acc[ii][3] + bi0.w);
            red_add_v4(p + 64, acc[ii][4] + bi1.x, acc[ii][5] + bi1.y,
                               acc[ii][6] + bi1.z, acc[ii][7] + bi1.w);
        }
    }
}

// ---------------------------------------------------------------------------
// K4: fused gate GEMM:  [agg/cnt | memory] (N x 512)  @  g_Bpack (512 x 1024) -> g_G
//     (mean-division folded into the A-tile load)
// ---------------------------------------------------------------------------
__global__ __launch_bounds__(256, 2)
void gru_gemm(const float* __restrict__ agg, const float* __restrict__ mem, int N)
{
    __shared__ __align__(16) float As[2][BK][PAD_A];
    __shared__ __align__(16) float Bs[2][BK][BN];
    const int tid = threadIdx.x;
    const int rowBase = blockIdx.x * BM;
    const int colBase = blockIdx.y * BN;

    const int ar = tid >> 2;
    const int ak = (tid & 3) << 2;
    const int bk = tid >> 5;
    const int bc = (tid & 31) << 2;
    const int trow = (tid >> 4) << 2;
    const int tcol = (tid & 15) << 2;

    const int r0 = rowBase + ar, r1 = rowBase + 64 + ar;
    const bool ok0 = r0 < N, ok1 = r1 < N;
    const float inv0 = ok0 ? 1.f / fmaxf((float)g_counts[r0], 1.f) : 0.f;
    const float inv1 = ok1 ? 1.f / fmaxf((float)g_counts[r1], 1.f) : 0.f;
    const float* Ga0 = agg + (size_t)r0 * DD + ak;
    const float* Ga1 = agg + (size_t)r1 * DD + ak;
    const float* Mm0 = mem + (size_t)r0 * DD + ak;
    const float* Mm1 = mem + (size_t)r1 * DD + ak;
    const float4 z4 = make_float4(0.f, 0.f, 0.f, 0.f);

    float acc[8][8];
#pragma unroll
    for (int i = 0; i < 8; i++)
#pragma unroll
        for (int j = 0; j < 8; j++) acc[i][j] = 0.f;

    float4 pa0, pa1, pb0, pb1;

    // A tile loader: k < 256 -> agg * inv, else memory
#define LOAD_A_GRU(k0) do {                                                            \
        if ((k0) < 256) {                                                              \
            pa0 = ok0 ? *(const float4*)(Ga0 + (k0)) : z4;                             \
            pa1 = ok1 ? *(const float4*)(Ga1 + (k0)) : z4;                             \
            pa0.x *= inv0; pa0.y *= inv0; pa0.z *= inv0; pa0.w *= inv0;                \
            pa1.x *= inv1; pa1.y *= inv1; pa1.z *= inv1; pa1.w *= inv1;                \
        } else {                                                                       \
            pa0 = ok0 ? *(const float4*)(Mm0 + ((k0) - 256)) : z4;                     \
            pa1 = ok1 ? *(const float4*)(Mm1 + ((k0) - 256)) : z4;                     \
        }                                                                              \
        pb0 = *(const float4*)(g_Bpack + (size_t)((k0) + bk)     * G_LD + colBase + bc); \
        pb1 = *(const float4*)(g_Bpack + (size_t)((k0) + 8 + bk) * G_LD + colBase + bc); \
    } while (0)

    LOAD_A_GRU(0);
    STORE_AB(0);
    __syncthreads();

    const int nk = GK / BK;
    for (int kt = 0; kt < nk; kt++) {
        const int buf = kt & 1;
        if (kt + 1 < nk) { LOAD_A_GRU((kt + 1) * BK); }
#pragma unroll
        for (int kk = 0; kk < BK; kk++) {
            float4 a0 = *(const float4*)&As[buf][kk][trow];
            float4 a1 = *(const float4*)&As[buf][kk][64 + trow];
            float4 b0 = *(const float4*)&Bs[buf][kk][tcol];
            float4 b1 = *(const float4*)&Bs[buf][kk][64 + tcol];
            float av[8] = {a0.x, a0.y, a0.z, a0.w, a1.x, a1.y, a1.z, a1.w};
            float bv[8] = {b0.x, b0.y, b0.z, b0.w, b1.x, b1.y, b1.z, b1.w};
#pragma unroll
            for (int i = 0; i < 8; i++)
#pragma unroll
                for (int j = 0; j < 8; j++)
                    acc[i][j] = fmaf(av[i], bv[j], acc[i][j]);
        }
        if (kt + 1 < nk) { const int nb = buf ^ 1; STORE_AB(nb); }
        __syncthreads();
    }

#pragma unroll
    for (int ii = 0; ii < 8; ii++) {
        const int r = rowBase + ((ii < 4) ? (trow + ii) : (64 + trow + (ii - 4)));
        if (r < N) {
            float* p = g_G + (size_t)r * G_LD + colBase + tcol;
            *(float4*)p = make_float4(acc[ii][0], acc[ii][1], acc[ii][2], acc[ii][3]);
            *(float4*)(p + 64) = make_float4(acc[ii][4], acc[ii][5], acc[ii][6], acc[ii][7]);
        }
    }
#undef LOAD_A_GRU
}

// ---------------------------------------------------------------------------
// K5: elementwise GRU + masked blend with memory -> d_out
// ---------------------------------------------------------------------------
__global__ void gru_final(const float* __restrict__ mem, const float* __restrict__ bg,
                          float* __restrict__ out, int N)
{
    int e = blockIdx.x * blockDim.x + threadIdx.x;
    if (e >= N * 64) return;
    const int i = e >> 6;
    const int j = (e & 63) << 2;
    const float* g = g_G + (size_t)i * G_LD + j;
    const float4 P  = *(const float4*)(g);
    const float4 Q  = *(const float4*)(g + 256);
    const float4 XN = *(const float4*)(g + 512);
    const float4 HN = *(const float4*)(g + 768);
    const float4 br = *(const float4*)(bg + j);
    const float4 bz = *(const float4*)(bg + 256 + j);
    const float4 bn = *(const float4*)(bg + 512 + j);
    const float4 m  = *(const float4*)(mem + (size_t)i * DD + j);
    const bool has = g_counts[i] > 0;
    float4 o;
#define GRU_LANE(L)                                                   \
    {                                                                 \
        float r = sigmoidf_(P.L + br.L);                              \
        float z = sigmoidf_(Q.L + bz.L);                              \
        float n = tanhf(XN.L + bn.L + r * HN.L);                      \
        float h = (1.f - z) * n + z * m.L;                            \
        o.L = has ? h : m.L;                                          \
    }
    GRU_LANE(x); GRU_LANE(y); GRU_LANE(z); GRU_LANE(w);
#undef GRU_LANE
    *(float4*)(out + (size_t)i * DD + j) = o;
}

// ---------------------------------------------------------------------------
// Launch
// ---------------------------------------------------------------------------
extern "C" void kernel_launch(void* const* d_in, const int* in_sizes, int n_in,
                              void* d_out, int out_size)
{
    const float* s_raw  = (const float*)d_in[0];
    const float* d_raw  = (const float*)d_in[1];
    const int*   s_src  = (const int*)  d_in[2];
    const int*   d_src  = (const int*)  d_in[3];
    // d_in[4], d_in[5] = s_t, d_t : dead in the reference output, skipped
    const float* W_src  = (const float*)d_in[6];
    const float* b_src  = (const float*)d_in[7];
    const float* W_dst  = (const float*)d_in[8];
    const float* b_dst  = (const float*)d_in[9];
    const float* W_gru  = (const float*)d_in[10];
    const float* U_gru  = (const float*)d_in[11];
    const float* b_gru  = (const float*)d_in[12];
    const float* memory = (const float*)d_in[13];

    const int M   = in_sizes[2];            // 200000 edges per store
    const int RAW = in_sizes[0] / M;        // 640
    const int N   = in_sizes[13] / DD;      // 100000 nodes
    float* out = (float*)d_out;

    // K0: zero agg (in d_out) + counts
    {
        const int n4 = N * (DD / 4);
        zero_kernel<<<cdiv(n4, 256), 256>>>((float4*)out, n4, N);
    }
    // K2: pack gate weights (independent of data flow order w.r.t. K0/K1)
    pack_kernel<<<cdiv(GK * G_LD, 256), 256>>>(W_gru, U_gru);
    // K1: counts
    count_kernel<<<cdiv(2 * M, 256), 256>>>(s_src, d_src, M);
    // K3: message GEMMs with fused scatter into agg (= d_out)
    {
        dim3 grid(cdiv(M, BM), DD / BN);
        msg_gemm_scatter<<<grid, 256>>>(s_raw, W_src, b_src, s_src, out, M, RAW);
        msg_gemm_scatter<<<grid, 256>>>(d_raw, W_dst, b_dst, d_src, out, M, RAW);
    }
    // K4: fused gate GEMM -> g_G
    {
        dim3 grid(cdiv(N, BM), G_LD / BN);
        gru_gemm<<<grid, 256>>>(out, memory, N);
    }
    // K5: GRU nonlinearity + masked write of new memory
    gru_final<<<cdiv(N * 64, 256), 256>>>(memory, b_gru, out, N);
}

// round 9
// speedup vs baseline: 2.4333x; 2.4333x over previous
#include <cuda_runtime.h>
#include <cstdint>

// Problem constants (fixed shapes for this dataset)
#define DD        256      // feature dim
#define G_LD      1024     // packed gate GEMM width (256 cols x 4 gates, interleaved)
#define GK        512      // packed gate GEMM K (agg 256 | memory 256)
#define NODES_MAX 100000

#define BM   128
#define BN   128
#define BK   16
#define PAD  136           // smem pitch: (8*tg+g)%32 distinct -> conflict-free frag LDS

// Static scratch — referenced ONLY inside device code (never passed from host!)
__device__ float g_agg[(size_t)NODES_MAX * DD];   // aggregated messages
__device__ float g_Bpack[GK * G_LD];              // packed+interleaved gate weights (tf32)
__device__ int   g_counts[NODES_MAX];

static inline int cdiv(int a, int b) { return (a + b - 1) / b; }

__device__ __forceinline__ uint32_t f2tf32(float x) {
    uint32_t u;
    asm("cvt.rna.tf32.f32 %0, %1;" : "=r"(u) : "f"(x));
    return u;
}
__device__ __forceinline__ float f2tf32f(float x) { return __uint_as_float(f2tf32(x)); }

__device__ __forceinline__ void mma_tf32(float c[4], const uint32_t a[4], const uint32_t b[2]) {
    asm volatile(
        "mma.sync.aligned.m16n8k8.row.col.f32.tf32.tf32.f32 "
        "{%0,%1,%2,%3}, {%4,%5,%6,%7}, {%8,%9}, {%0,%1,%2,%3};"
        : "+f"(c[0]), "+f"(c[1]), "+f"(c[2]), "+f"(c[3])
        : "r"(a[0]), "r"(a[1]), "r"(a[2]), "r"(a[3]), "r"(b[0]), "r"(b[1]));
}

__device__ __forceinline__ void red_add_v2(float* p, float a, float b) {
    asm volatile("red.global.add.v2.f32 [%0], {%1, %2};" :: "l"(p), "f"(a), "f"(b) : "memory");
}

__device__ __forceinline__ float sigmoidf_(float x) { return 1.f / (1.f + expf(-x)); }

// ---------------------------------------------------------------------------
// K0: zero g_agg and g_counts
// ---------------------------------------------------------------------------
__global__ void zero_kernel(int n4, int N) {
    int i = blockIdx.x * blockDim.x + threadIdx.x;
    if (i < n4) ((float4*)g_agg)[i] = make_float4(0.f, 0.f, 0.f, 0.f);
    if (i < N)  g_counts[i] = 0;
}

// ---------------------------------------------------------------------------
// K1: per-node message counts (both edge stores)
// ---------------------------------------------------------------------------
__global__ void count_kernel(const int* __restrict__ s_src,
                             const int* __restrict__ d_src, int M) {
    int e = blockIdx.x * blockDim.x + threadIdx.x;
    if (e < 2 * M) {
        int node = (e < M) ? s_src[e] : d_src[e - M];
        atomicAdd(&g_counts[node], 1);
    }
}

// ---------------------------------------------------------------------------
// K2: pack B for the fused gate GEMM, gate-interleaved + tf32-rounded.
//   packed col j = f*4 + gate ; gates: 0=r (W|U), 1=z (W|U), 2=xn (W|0), 3=hn (0|U)
// ---------------------------------------------------------------------------
__global__ void pack_kernel(const float* __restrict__ Wg, const float* __restrict__ Ug) {
    int idx = blockIdx.x * blockDim.x + threadIdx.x;
    if (idx >= GK * G_LD) return;
    int k = idx >> 10, j = idx & (G_LD - 1);
    int f = j >> 2, gate = j & 3;
    float v = 0.f;
    if (gate == 0)      v = (k < 256) ? Wg[k * 768 + f]       : Ug[(k - 256) * 768 + f];
    else if (gate == 1) v = (k < 256) ? Wg[k * 768 + 256 + f] : Ug[(k - 256) * 768 + 256 + f];
    else if (gate == 2) v = (k < 256) ? Wg[k * 768 + 512 + f] : 0.f;
    else                v = (k < 256) ? 0.f                   : Ug[(k - 256) * 768 + 512 + f];
    g_Bpack[idx] = f2tf32f(v);
}

// ---------------------------------------------------------------------------
// K3: tensor-core message GEMM (raw[M,K] @ W[K,256] + b), fused scatter -> g_agg
// ---------------------------------------------------------------------------
__global__ __launch_bounds__(256)
void msg_gemm_tc(const float* __restrict__ A, const float* __restrict__ B,
                 const float* __restrict__ bias, const int* __restrict__ src,
                 int M, int K)
{
    __shared__ __align__(16) float As[2][BK][PAD];   // A[m][k] staged as [k][m]
    __shared__ __align__(16) float Bs[2][BK][PAD];   // B[k][n] staged as [k][n]

    const int tid  = threadIdx.x;
    const int lane = tid & 31;
    const int warp = tid >> 5;
    const int g    = lane >> 2;        // 0..7
    const int tg   = lane & 3;         // 0..3
    const int warpM = warp & 1;        // 2 warps over M
    const int warpN = warp >> 1;       // 4 warps over N
    const int rowBase = blockIdx.x * BM;
    const int colBase = blockIdx.y * BN;

    // staging indices
    const int ar = tid >> 2;           // 0..63
    const int ak = (tid & 3) << 2;     // 0,4,8,12
    const int bk = tid >> 5;           // 0..7
    const int bc = (tid & 31) << 2;    // 0..124

    const int r0 = rowBase + ar, r1 = rowBase + 64 + ar;
    const bool ok0 = r0 < M, ok1 = r1 < M;
    const float* A0 = A + (size_t)r0 * K + ak;
    const float* A1 = A + (size_t)r1 * K + ak;
    const float4 z4 = make_float4(0.f, 0.f, 0.f, 0.f);

    float acc[4][4][4];
#pragma unroll
    for (int mt = 0; mt < 4; mt++)
#pragma unroll
        for (int nt = 0; nt < 4; nt++)
#pragma unroll
            for (int i = 0; i < 4; i++) acc[mt][nt][i] = 0.f;

    float4 pa0, pa1, pb0, pb1;

#define STAGE(nb) do {                                                                 \
    As[nb][ak+0][ar]    = f2tf32f(pa0.x); As[nb][ak+1][ar]    = f2tf32f(pa0.y);        \
    As[nb][ak+2][ar]    = f2tf32f(pa0.z); As[nb][ak+3][ar]    = f2tf32f(pa0.w);        \
    As[nb][ak+0][64+ar] = f2tf32f(pa1.x); As[nb][ak+1][64+ar] = f2tf32f(pa1.y);        \
    As[nb][ak+2][64+ar] = f2tf32f(pa1.z); As[nb][ak+3][64+ar] = f2tf32f(pa1.w);        \
    Bs[nb][bk][bc+0]   = f2tf32f(pb0.x); Bs[nb][bk][bc+1]   = f2tf32f(pb0.y);          \
    Bs[nb][bk][bc+2]   = f2tf32f(pb0.z); Bs[nb][bk][bc+3]   = f2tf32f(pb0.w);          \
    Bs[nb][8+bk][bc+0] = f2tf32f(pb1.x); Bs[nb][8+bk][bc+1] = f2tf32f(pb1.y);          \
    Bs[nb][8+bk][bc+2] = f2tf32f(pb1.z); Bs[nb][8+bk][bc+3] = f2tf32f(pb1.w);          \
} while (0)

    pa0 = ok0 ? *(const float4*)(A0) : z4;
    pa1 = ok1 ? *(const float4*)(A1) : z4;
    pb0 = *(const float4*)(B + (size_t)(bk)     * DD + colBase + bc);
    pb1 = *(const float4*)(B + (size_t)(8 + bk) * DD + colBase + bc);
    STAGE(0);
    __syncthreads();

    const int nk = K / BK;
    for (int kt = 0; kt < nk; kt++) {
        const int buf = kt & 1;
        if (kt + 1 < nk) {
            const int k0 = (kt + 1) * BK;
            pa0 = ok0 ? *(const float4*)(A0 + k0) : z4;
            pa1 = ok1 ? *(const float4*)(A1 + k0) : z4;
            pb0 = *(const float4*)(B + (size_t)(k0 + bk)     * DD + colBase + bc);
            pb1 = *(const float4*)(B + (size_t)(k0 + 8 + bk) * DD + colBase + bc);
        }
        const uint32_t* Au = (const uint32_t*)&As[buf][0][0];
        const uint32_t* Bu = (const uint32_t*)&Bs[buf][0][0];
#pragma unroll
        for (int s = 0; s < 2; s++) {
            const int k0 = s * 8;
            uint32_t af[4][4], bf[4][2];
#pragma unroll
            for (int mt = 0; mt < 4; mt++) {
                const int m = warpM * 64 + mt * 16 + g;
                af[mt][0] = Au[(k0 + tg)     * PAD + m];
                af[mt][1] = Au[(k0 + tg)     * PAD + m + 8];
                af[mt][2] = Au[(k0 + tg + 4) * PAD + m];
                af[mt][3] = Au[(k0 + tg + 4) * PAD + m + 8];
            }
#pragma unroll
            for (int nt = 0; nt < 4; nt++) {
                const int n = warpN * 32 + nt * 8 + g;
                bf[nt][0] = Bu[(k0 + tg)     * PAD + n];
                bf[nt][1] = Bu[(k0 + tg + 4) * PAD + n];
            }
#pragma unroll
            for (int mt = 0; mt < 4; mt++)
#pragma unroll
                for (int nt = 0; nt < 4; nt++)
                    mma_tf32(acc[mt][nt], af[mt], bf[nt]);
        }
        if (kt + 1 < nk) { STAGE(buf ^ 1); }
        __syncthreads();
    }
#undef STAGE

    // Epilogue: scatter-add (+bias) into g_agg via red.global.add.v2
#pragma unroll
    for (int mt = 0; mt < 4; mt++) {
        const int rA = rowBase + warpM * 64 + mt * 16 + g;
        const int rB = rA + 8;
        const bool okA = rA < M, okB = rB < M;
        const int nodeA = okA ? __ldg(&src[rA]) : 0;
        const int nodeB = okB ? __ldg(&src[rB]) : 0;
#pragma unroll
        for (int nt = 0; nt < 4; nt++) {
            const int c = colBase + warpN * 32 + nt * 8 + 2 * tg;
            const float b0v = __ldg(&bias[c]), b1v = __ldg(&bias[c + 1]);
            if (okA) red_add_v2(g_agg + (size_t)nodeA * DD + c,
                                acc[mt][nt][0] + b0v, acc[mt][nt][1] + b1v);
            if (okB) red_add_v2(g_agg + (size_t)nodeB * DD + c,
                                acc[mt][nt][2] + b0v, acc[mt][nt][3] + b1v);
        }
    }
}

// ---------------------------------------------------------------------------
// K4: tensor-core gate GEMM [g_agg/cnt | memory](N x 512) @ g_Bpack(512 x 1024)
//     with fully fused GRU epilogue -> writes new_memory directly to out.
// ---------------------------------------------------------------------------
__global__ __launch_bounds__(256)
void gru_gemm_tc(const float* __restrict__ mem, const float* __restrict__ bg,
                 float* __restrict__ out, int N)
{
    __shared__ __align__(16) float As[2][BK][PAD];
    __shared__ __align__(16) float Bs[2][BK][PAD];

    const int tid  = threadIdx.x;
    const int lane = tid & 31;
    const int warp = tid >> 5;
    const int g    = lane >> 2;
    const int tg   = lane & 3;
    const int warpM = warp & 1;
    const int warpN = warp >> 1;
    const int rowBase = blockIdx.x * BM;
    const int colBase = blockIdx.y * BN;

    const int ar = tid >> 2;
    const int ak = (tid & 3) << 2;
    const int bk = tid >> 5;
    const int bc = (tid & 31) << 2;

    const int r0 = rowBase + ar, r1 = rowBase + 64 + ar;
    const bool ok0 = r0 < N, ok1 = r1 < N;
    const float inv0 = ok0 ? 1.f / fmaxf((float)g_counts[r0], 1.f) : 0.f;
    const float inv1 = ok1 ? 1.f / fmaxf((float)g_counts[r1], 1.f) : 0.f;
    const float* Ga0 = g_agg + (size_t)r0 * DD + ak;
    const float* Ga1 = g_agg + (size_t)r1 * DD + ak;
    const float* Mm0 = mem + (size_t)r0 * DD + ak;
    const float* Mm1 = mem + (size_t)r1 * DD + ak;
    const float4 z4 = make_float4(0.f, 0.f, 0.f, 0.f);

    float acc[4][4][4];
#pragma unroll
    for (int mt = 0; mt < 4; mt++)
#pragma unroll
        for (int nt = 0; nt < 4; nt++)
#pragma unroll
            for (int i = 0; i < 4; i++) acc[mt][nt][i] = 0.f;

    float4 pa0, pa1, pb0, pb1;

#define LOAD_AB(k0) do {                                                                \
        if ((k0) < 256) {                                                               \
            pa0 = ok0 ? *(const float4*)(Ga0 + (k0)) : z4;                              \
            pa1 = ok1 ? *(const float4*)(Ga1 + (k0)) : z4;                              \
            pa0.x *= inv0; pa0.y *= inv0; pa0.z *= inv0; pa0.w *= inv0;                 \
            pa1.x *= inv1; pa1.y *= inv1; pa1.z *= inv1; pa1.w *= inv1;                 \
        } else {                                                                        \
            pa0 = ok0 ? *(const float4*)(Mm0 + ((k0) - 256)) : z4;                      \
            pa1 = ok1 ? *(const float4*)(Mm1 + ((k0) - 256)) : z4;                      \
        }                                                                               \
        pb0 = *(const float4*)(g_Bpack + (size_t)((k0) + bk)     * G_LD + colBase + bc);\
        pb1 = *(const float4*)(g_Bpack + (size_t)((k0) + 8 + bk) * G_LD + colBase + bc);\
    } while (0)

#define STAGE(nb) do {                                                                 \
    As[nb][ak+0][ar]    = f2tf32f(pa0.x); As[nb][ak+1][ar]    = f2tf32f(pa0.y);        \
    As[nb][ak+2][ar]    = f2tf32f(pa0.z); As[nb][ak+3][ar]    = f2tf32f(pa0.w);        \
    As[nb][ak+0][64+ar] = f2tf32f(pa1.x); As[nb][ak+1][64+ar] = f2tf32f(pa1.y);        \
    As[nb][ak+2][64+ar] = f2tf32f(pa1.z); As[nb][ak+3][64+ar] = f2tf32f(pa1.w);        \
    *(float4*)&Bs[nb][bk][bc]   = pb0;  /* g_Bpack already tf32-rounded */             \
    *(float4*)&Bs[nb][8+bk][bc] = pb1;                                                 \
} while (0)

    LOAD_AB(0);
    STAGE(0);
    __syncthreads();

    const int nk = GK / BK;
    for (int kt = 0; kt < nk; kt++) {
        const int buf = kt & 1;
        if (kt + 1 < nk) { LOAD_AB((kt + 1) * BK); }
        const uint32_t* Au = (const uint32_t*)&As[buf][0][0];
        const uint32_t* Bu = (const uint32_t*)&Bs[buf][0][0];
#pragma unroll
        for (int s = 0; s < 2; s++) {
            const int k0 = s * 8;
            uint32_t af[4][4], bf[4][2];
#pragma unroll
            for (int mt = 0; mt < 4; mt++) {
                const int m = warpM * 64 + mt * 16 + g;
                af[mt][0] = Au[(k0 + tg)     * PAD + m];
                af[mt][1] = Au[(k0 + tg)     * PAD + m + 8];
                af[mt][2] = Au[(k0 + tg + 4) * PAD + m];
                af[mt][3] = Au[(k0 + tg + 4) * PAD + m + 8];
            }
#pragma unroll
            for (int nt = 0; nt < 4; nt++) {
                const int n = warpN * 32 + nt * 8 + g;
                bf[nt][0] = Bu[(k0 + tg)     * PAD + n];
                bf[nt][1] = Bu[(k0 + tg + 4) * PAD + n];
            }
#pragma unroll
            for (int mt = 0; mt < 4; mt++)
#pragma unroll
                for (int nt = 0; nt < 4; nt++)
                    mma_tf32(acc[mt][nt], af[mt], bf[nt]);
        }
        if (kt + 1 < nk) { STAGE(buf ^ 1); }
        __syncthreads();
    }
#undef STAGE
#undef LOAD_AB

    // Fused GRU epilogue.
    // Packed col c = 4*f + gate. Even-tg thread owns (r,z) preacts of feature f;
    // its lane^1 partner owns (xn,hn). One shfl pairs them.
#pragma unroll
    for (int mt = 0; mt < 4; mt++) {
        const int rA = rowBase + warpM * 64 + mt * 16 + g;
        const int rB = rA + 8;
#pragma unroll
        for (int nt = 0; nt < 4; nt++) {
            float o0 = __shfl_xor_sync(0xffffffffu, acc[mt][nt][0], 1);
            float o1 = __shfl_xor_sync(0xffffffffu, acc[mt][nt][1], 1);
            float o2 = __shfl_xor_sync(0xffffffffu, acc[mt][nt][2], 1);
            float o3 = __shfl_xor_sync(0xffffffffu, acc[mt][nt][3], 1);
            if ((tg & 1) == 0) {
                const int c = colBase + warpN * 32 + nt * 8 + 2 * tg;
                const int f = c >> 2;
                const float br = __ldg(&bg[f]);
                const float bz = __ldg(&bg[256 + f]);
                const float bn = __ldg(&bg[512 + f]);
                if (rA < N) {
                    const float m = __ldg(&mem[(size_t)rA * DD + f]);
                    if (g_counts[rA] > 0) {
                        const float r = sigmoidf_(acc[mt][nt][0] + br);
                        const float z = sigmoidf_(acc[mt][nt][1] + bz);
                        const float n = tanhf(o0 + bn + r * o1);
                        out[(size_t)rA * DD + f] = (1.f - z) * n + z * m;
                    } else {
                        out[(size_t)rA * DD + f] = m;
                    }
                }
                if (rB < N) {
                    const float m = __ldg(&mem[(size_t)rB * DD + f]);
                    if (g_counts[rB] > 0) {
                        const float r = sigmoidf_(acc[mt][nt][2] + br);
                        const float z = sigmoidf_(acc[mt][nt][3] + bz);
                        const float n = tanhf(o2 + bn + r * o3);
                        out[(size_t)rB * DD + f] = (1.f - z) * n + z * m;
                    } else {
                        out[(size_t)rB * DD + f] = m;
                    }
                }
            }
        }
    }
}

// ---------------------------------------------------------------------------
// Launch
// ---------------------------------------------------------------------------
extern "C" void kernel_launch(void* const* d_in, const int* in_sizes, int n_in,
                              void* d_out, int out_size)
{
    const float* s_raw  = (const float*)d_in[0];
    const float* d_raw  = (const float*)d_in[1];
    const int*   s_src  = (const int*)  d_in[2];
    const int*   d_src  = (const int*)  d_in[3];
    // d_in[4], d_in[5] = s_t, d_t : dead in the reference output, skipped
    const float* W_src  = (const float*)d_in[6];
    const float* b_src  = (const float*)d_in[7];
    const float* W_dst  = (const float*)d_in[8];
    const float* b_dst  = (const float*)d_in[9];
    const float* W_gru  = (const float*)d_in[10];
    const float* U_gru  = (const float*)d_in[11];
    const float* b_gru  = (const float*)d_in[12];
    const float* memory = (const float*)d_in[13];

    const int M   = in_sizes[2];            // 200000 edges per store
    const int RAW = in_sizes[0] / M;        // 640
    const int N   = in_sizes[13] / DD;      // 100000 nodes
    float* out = (float*)d_out;
    const int n4 = N * (DD / 4);

    // K0: zero g_agg + counts
    zero_kernel<<<cdiv(n4, 256), 256>>>(n4, N);
    // K2: pack + tf32-round gate weights
    pack_kernel<<<cdiv(GK * G_LD, 256), 256>>>(W_gru, U_gru);
    // K1: counts
    count_kernel<<<cdiv(2 * M, 256), 256>>>(s_src, d_src, M);
    // K3: message GEMMs with fused scatter into g_agg
    {
        dim3 grid(cdiv(M, BM), DD / BN);
        msg_gemm_tc<<<grid, 256>>>(s_raw, W_src, b_src, s_src, M, RAW);
        msg_gemm_tc<<<grid, 256>>>(d_raw, W_dst, b_dst, d_src, M, RAW);
    }
    // K4: gate GEMM + fully fused GRU epilogue -> final new_memory in d_out
    {
        dim3 grid(cdiv(N, BM), G_LD / BN);
        gru_gemm_tc<<<grid, 256>>>(memory, b_gru, out, N);
    }
}

// round 12
// speedup vs baseline: 2.5549x; 1.0500x over previous
#include <cuda_runtime.h>
#include <cstdint>

// Problem constants (fixed shapes for this dataset)
#define DD        256      // feature dim
#define G_LD      1024     // packed gate GEMM width (256 cols x 4 gates, interleaved)
#define GK        512      // packed gate GEMM K (agg 256 | memory 256)
#define RAW_K     640      // raw message dim
#define NODES_MAX 100000

#define BM    128
#define BN    128
#define BK    16
#define PADA  20           // A pitch (row-major [m][k]): (20g+tg)%32 all distinct
#define PADB  136          // B pitch ([k][n]): (8tg+g)%32 all distinct

// Static scratch — referenced ONLY inside device code (never passed from host!)
__device__ float g_agg[(size_t)NODES_MAX * DD];   // aggregated messages
__device__ float g_Bpack[GK * G_LD];              // packed+interleaved gate weights (tf32)
__device__ float g_W[2 * RAW_K * DD];             // tf32-rounded W_src | W_dst
__device__ int   g_counts[NODES_MAX];

static inline int cdiv(int a, int b) { return (a + b - 1) / b; }

__device__ __forceinline__ uint32_t f2tf32(float x) {
    uint32_t u;
    asm("cvt.rna.tf32.f32 %0, %1;" : "=r"(u) : "f"(x));
    return u;
}
__device__ __forceinline__ float f2tf32f(float x) { return __uint_as_float(f2tf32(x)); }

__device__ __forceinline__ void mma_tf32(float c[4], const uint32_t a[4], const uint32_t b[2]) {
    asm volatile(
        "mma.sync.aligned.m16n8k8.row.col.f32.tf32.tf32.f32 "
        "{%0,%1,%2,%3}, {%4,%5,%6,%7}, {%8,%9}, {%0,%1,%2,%3};"
        : "+f"(c[0]), "+f"(c[1]), "+f"(c[2]), "+f"(c[3])
        : "r"(a[0]), "r"(a[1]), "r"(a[2]), "r"(a[3]), "r"(b[0]), "r"(b[1]));
}

__device__ __forceinline__ void red_add_v2(float* p, float a, float b) {
    asm volatile("red.global.add.v2.f32 [%0], {%1, %2};" :: "l"(p), "f"(a), "f"(b) : "memory");
}

__device__ __forceinline__ float sigmoidf_(float x) { return 1.f / (1.f + expf(-x)); }

// ---------------------------------------------------------------------------
// K0: zero g_agg and g_counts
// ---------------------------------------------------------------------------
__global__ void zero_kernel(int n4, int N) {
    int i = blockIdx.x * blockDim.x + threadIdx.x;
    if (i < n4) ((float4*)g_agg)[i] = make_float4(0.f, 0.f, 0.f, 0.f);
    if (i < N)  g_counts[i] = 0;
}

// ---------------------------------------------------------------------------
// K1: per-node message counts (both edge stores)
// ---------------------------------------------------------------------------
__global__ void count_kernel(const int* __restrict__ s_src,
                             const int* __restrict__ d_src, int M) {
    int e = blockIdx.x * blockDim.x + threadIdx.x;
    if (e < 2 * M) {
        int node = (e < M) ? s_src[e] : d_src[e - M];
        atomicAdd(&g_counts[node], 1);
    }
}

// ---------------------------------------------------------------------------
// K2a: pack gate weights (gate-interleaved + tf32-rounded)
//   packed col j = f*4 + gate ; gates: 0=r (W|U), 1=z (W|U), 2=xn (W|0), 3=hn (0|U)
// ---------------------------------------------------------------------------
__global__ void pack_kernel(const float* __restrict__ Wg, const float* __restrict__ Ug) {
    int idx = blockIdx.x * blockDim.x + threadIdx.x;
    if (idx >= GK * G_LD) return;
    int k = idx >> 10, j = idx & (G_LD - 1);
    int f = j >> 2, gate = j & 3;
    float v = 0.f;
    if (gate == 0)      v = (k < 256) ? Wg[k * 768 + f]       : Ug[(k - 256) * 768 + f];
    else if (gate == 1) v = (k < 256) ? Wg[k * 768 + 256 + f] : Ug[(k - 256) * 768 + 256 + f];
    else if (gate == 2) v = (k < 256) ? Wg[k * 768 + 512 + f] : 0.f;
    else                v = (k < 256) ? 0.f                   : Ug[(k - 256) * 768 + 512 + f];
    g_Bpack[idx] = f2tf32f(v);
}

// K2b: tf32-round the message weights into scratch (so hot loop stages B w/o cvt)
__global__ void pack_w_kernel(const float* __restrict__ Ws, const float* __restrict__ Wd) {
    int idx = blockIdx.x * blockDim.x + threadIdx.x;
    const int n = RAW_K * DD;
    if (idx < n)            g_W[idx]     = f2tf32f(Ws[idx]);
    else if (idx < 2 * n)   g_W[idx]     = f2tf32f(Wd[idx - n]);
}

// ---------------------------------------------------------------------------
// K3: tensor-core message GEMM (raw[M,640] @ g_W[wsel] + b), fused scatter -> g_agg
// ---------------------------------------------------------------------------
__global__ __launch_bounds__(256)
void msg_gemm_tc(const float* __restrict__ A, int wsel,
                 const float* __restrict__ bias, const int* __restrict__ src,
                 int M)
{
    __shared__ __align__(16) float As[2][BM][PADA];   // row-major [m][k]
    __shared__ __align__(16) float Bs[2][BK][PADB];   // [k][n]

    const float* __restrict__ B = g_W + (size_t)wsel * RAW_K * DD;

    const int tid  = threadIdx.x;
    const int lane = tid & 31;
    const int warp = tid >> 5;
    const int g    = lane >> 2;        // 0..7
    const int tg   = lane & 3;         // 0..3
    const int warpM = warp & 1;        // 2 warps over M
    const int warpN = warp >> 1;       // 4 warps over N
    const int rowBase = blockIdx.x * BM;
    const int colBase = blockIdx.y * BN;

    // staging indices
    const int ar = tid >> 2;           // 0..63
    const int ak = (tid & 3) << 2;     // 0,4,8,12
    const int bk = tid >> 5;           // 0..7
    const int bc = (tid & 31) << 2;    // 0..124

    const int r0 = rowBase + ar, r1 = rowBase + 64 + ar;
    const bool ok0 = r0 < M, ok1 = r1 < M;
    const float* A0 = A + (size_t)r0 * RAW_K + ak;
    const float* A1 = A + (size_t)r1 * RAW_K + ak;
    const float4 z4 = make_float4(0.f, 0.f, 0.f, 0.f);

    float acc[4][4][4];
#pragma unroll
    for (int mt = 0; mt < 4; mt++)
#pragma unroll
        for (int nt = 0; nt < 4; nt++)
#pragma unroll
            for (int i = 0; i < 4; i++) acc[mt][nt][i] = 0.f;

    float4 pa0, pa1, pb0, pb1;

#define STAGE(nb) do {                                                                   \
    *(float4*)&As[nb][ar][ak]      = make_float4(f2tf32f(pa0.x), f2tf32f(pa0.y),         \
                                                 f2tf32f(pa0.z), f2tf32f(pa0.w));        \
    *(float4*)&As[nb][64 + ar][ak] = make_float4(f2tf32f(pa1.x), f2tf32f(pa1.y),         \
                                                 f2tf32f(pa1.z), f2tf32f(pa1.w));        \
    *(float4*)&Bs[nb][bk][bc]      = pb0;   /* g_W already tf32-rounded */               \
    *(float4*)&Bs[nb][8 + bk][bc]  = pb1;                                                \
} while (0)

    pa0 = ok0 ? *(const float4*)(A0) : z4;
    pa1 = ok1 ? *(const float4*)(A1) : z4;
    pb0 = *(const float4*)(B + (size_t)(bk)     * DD + colBase + bc);
    pb1 = *(const float4*)(B + (size_t)(8 + bk) * DD + colBase + bc);
    STAGE(0);
    __syncthreads();

    const int nk = RAW_K / BK;
    for (int kt = 0; kt < nk; kt++) {
        const int buf = kt & 1;
        if (kt + 1 < nk) {
            const int k0 = (kt + 1) * BK;
            pa0 = ok0 ? *(const float4*)(A0 + k0) : z4;
            pa1 = ok1 ? *(const float4*)(A1 + k0) : z4;
            pb0 = *(const float4*)(B + (size_t)(k0 + bk)     * DD + colBase + bc);
            pb1 = *(const float4*)(B + (size_t)(k0 + 8 + bk) * DD + colBase + bc);
        }
        const uint32_t* Au = (const uint32_t*)&As[buf][0][0];
        const uint32_t* Bu = (const uint32_t*)&Bs[buf][0][0];
#pragma unroll
        for (int s = 0; s < 2; s++) {
            const int k0 = s * 8;
            uint32_t af[4][4], bf[4][2];
#pragma unroll
            for (int mt = 0; mt < 4; mt++) {
                const int m = warpM * 64 + mt * 16 + g;
                af[mt][0] = Au[(m)     * PADA + k0 + tg];
                af[mt][1] = Au[(m + 8) * PADA + k0 + tg];
                af[mt][2] = Au[(m)     * PADA + k0 + tg + 4];
                af[mt][3] = Au[(m + 8) * PADA + k0 + tg + 4];
            }
#pragma unroll
            for (int nt = 0; nt < 4; nt++) {
                const int n = warpN * 32 + nt * 8 + g;
                bf[nt][0] = Bu[(k0 + tg)     * PADB + n];
                bf[nt][1] = Bu[(k0 + tg + 4) * PADB + n];
            }
#pragma unroll
            for (int mt = 0; mt < 4; mt++)
#pragma unroll
                for (int nt = 0; nt < 4; nt++)
                    mma_tf32(acc[mt][nt], af[mt], bf[nt]);
        }
        if (kt + 1 < nk) { STAGE(buf ^ 1); }
        __syncthreads();
    }
#undef STAGE

    // Epilogue: scatter-add (+bias) into g_agg via red.global.add.v2
#pragma unroll
    for (int mt = 0; mt < 4; mt++) {
        const int rA = rowBase + warpM * 64 + mt * 16 + g;
        const int rB = rA + 8;
        const bool okA = rA < M, okB = rB < M;
        const int nodeA = okA ? __ldg(&src[rA]) : 0;
        const int nodeB = okB ? __ldg(&src[rB]) : 0;
#pragma unroll
        for (int nt = 0; nt < 4; nt++) {
            const int c = colBase + warpN * 32 + nt * 8 + 2 * tg;
            const float b0v = __ldg(&bias[c]), b1v = __ldg(&bias[c + 1]);
            if (okA) red_add_v2(g_agg + (size_t)nodeA * DD + c,
                                acc[mt][nt][0] + b0v, acc[mt][nt][1] + b1v);
            if (okB) red_add_v2(g_agg + (size_t)nodeB * DD + c,
                                acc[mt][nt][2] + b0v, acc[mt][nt][3] + b1v);
        }
    }
}

// ---------------------------------------------------------------------------
// K4: tensor-core gate GEMM [g_agg/cnt | memory](N x 512) @ g_Bpack(512 x 1024)
//     with fully fused GRU epilogue -> writes new_memory directly to out.
// ---------------------------------------------------------------------------
__global__ __launch_bounds__(256)
void gru_gemm_tc(const float* __restrict__ mem, const float* __restrict__ bg,
                 float* __restrict__ out, int N)
{
    __shared__ __align__(16) float As[2][BM][PADA];
    __shared__ __align__(16) float Bs[2][BK][PADB];

    const int tid  = threadIdx.x;
    const int lane = tid & 31;
    const int warp = tid >> 5;
    const int g    = lane >> 2;
    const int tg   = lane & 3;
    const int warpM = warp & 1;
    const int warpN = warp >> 1;
    const int rowBase = blockIdx.x * BM;
    const int colBase = blockIdx.y * BN;

    const int ar = tid >> 2;
    const int ak = (tid & 3) << 2;
    const int bk = tid >> 5;
    const int bc = (tid & 31) << 2;

    const int r0 = rowBase + ar, r1 = rowBase + 64 + ar;
    const bool ok0 = r0 < N, ok1 = r1 < N;
    const float inv0 = ok0 ? 1.f / fmaxf((float)g_counts[r0], 1.f) : 0.f;
    const float inv1 = ok1 ? 1.f / fmaxf((float)g_counts[r1], 1.f) : 0.f;
    const float* Ga0 = g_agg + (size_t)r0 * DD + ak;
    const float* Ga1 = g_agg + (size_t)r1 * DD + ak;
    const float* Mm0 = mem + (size_t)r0 * DD + ak;
    const float* Mm1 = mem + (size_t)r1 * DD + ak;
    const float4 z4 = make_float4(0.f, 0.f, 0.f, 0.f);

    float acc[4][4][4];
#pragma unroll
    for (int mt = 0; mt < 4; mt++)
#pragma unroll
        for (int nt = 0; nt < 4; nt++)
#pragma unroll
            for (int i = 0; i < 4; i++) acc[mt][nt][i] = 0.f;

    float4 pa0, pa1, pb0, pb1;

#define LOAD_AB(k0) do {                                                                \
        if ((k0) < 256) {                                                               \
            pa0 = ok0 ? *(const float4*)(Ga0 + (k0)) : z4;                              \
            pa1 = ok1 ? *(const float4*)(Ga1 + (k0)) : z4;                              \
            pa0.x *= inv0; pa0.y *= inv0; pa0.z *= inv0; pa0.w *= inv0;                 \
            pa1.x *= inv1; pa1.y *= inv1; pa1.z *= inv1; pa1.w *= inv1;                 \
        } else {                                                                        \
            pa0 = ok0 ? *(const float4*)(Mm0 + ((k0) - 256)) : z4;                      \
            pa1 = ok1 ? *(const float4*)(Mm1 + ((k0) - 256)) : z4;                      \
        }                                                                               \
        pb0 = *(const float4*)(g_Bpack + (size_t)((k0) + bk)     * G_LD + colBase + bc);\
        pb1 = *(const float4*)(g_Bpack + (size_t)((k0) + 8 + bk) * G_LD + colBase + bc);\
    } while (0)

#define STAGE(nb) do {                                                                   \
    *(float4*)&As[nb][ar][ak]      = make_float4(f2tf32f(pa0.x), f2tf32f(pa0.y),         \
                                                 f2tf32f(pa0.z), f2tf32f(pa0.w));        \
    *(float4*)&As[nb][64 + ar][ak] = make_float4(f2tf32f(pa1.x), f2tf32f(pa1.y),         \
                                                 f2tf32f(pa1.z), f2tf32f(pa1.w));        \
    *(float4*)&Bs[nb][bk][bc]      = pb0;   /* g_Bpack already tf32-rounded */           \
    *(float4*)&Bs[nb][8 + bk][bc]  = pb1;                                                \
} while (0)

    LOAD_AB(0);
    STAGE(0);
    __syncthreads();

    const int nk = GK / BK;
    for (int kt = 0; kt < nk; kt++) {
        const int buf = kt & 1;
        if (kt + 1 < nk) { LOAD_AB((kt + 1) * BK); }
        const uint32_t* Au = (const uint32_t*)&As[buf][0][0];
        const uint32_t* Bu = (const uint32_t*)&Bs[buf][0][0];
#pragma unroll
        for (int s = 0; s < 2; s++) {
            const int k0 = s * 8;
            uint32_t af[4][4], bf[4][2];
#pragma unroll
            for (int mt = 0; mt < 4; mt++) {
                const int m = warpM * 64 + mt * 16 + g;
                af[mt][0] = Au[(m)     * PADA + k0 + tg];
                af[mt][1] = Au[(m + 8) * PADA + k0 + tg];
                af[mt][2] = Au[(m)     * PADA + k0 + tg + 4];
                af[mt][3] = Au[(m + 8) * PADA + k0 + tg + 4];
            }
#pragma unroll
            for (int nt = 0; nt < 4; nt++) {
                const int n = warpN * 32 + nt * 8 + g;
                bf[nt][0] = Bu[(k0 + tg)     * PADB + n];
                bf[nt][1] = Bu[(k0 + tg + 4) * PADB + n];
            }
#pragma unroll
            for (int mt = 0; mt < 4; mt++)
#pragma unroll
                for (int nt = 0; nt < 4; nt++)
                    mma_tf32(acc[mt][nt], af[mt], bf[nt]);
        }
        if (kt + 1 < nk) { STAGE(buf ^ 1); }
        __syncthreads();
    }
#undef STAGE
#undef LOAD_AB

    // Fused GRU epilogue.
    // Packed col c = 4*f + gate. Even-tg thread owns (r,z) preacts of feature f;
    // its lane^1 partner owns (xn,hn). One shfl pairs them.
#pragma unroll
    for (int mt = 0; mt < 4; mt++) {
        const int rA = rowBase + warpM * 64 + mt * 16 + g;
        const int rB = rA + 8;
#pragma unroll
        for (int nt = 0; nt < 4; nt++) {
            float o0 = __shfl_xor_sync(0xffffffffu, acc[mt][nt][0], 1);
            float o1 = __shfl_xor_sync(0xffffffffu, acc[mt][nt][1], 1);
            float o2 = __shfl_xor_sync(0xffffffffu, acc[mt][nt][2], 1);
            float o3 = __shfl_xor_sync(0xffffffffu, acc[mt][nt][3], 1);
            if ((tg & 1) == 0) {
                const int c = colBase + warpN * 32 + nt * 8 + 2 * tg;
                const int f = c >> 2;
                const float br = __ldg(&bg[f]);
                const float bz = __ldg(&bg[256 + f]);
                const float bn = __ldg(&bg[512 + f]);
                if (rA < N) {
                    const float m = __ldg(&mem[(size_t)rA * DD + f]);
                    if (g_counts[rA] > 0) {
                        const float r = sigmoidf_(acc[mt][nt][0] + br);
                        const float z = sigmoidf_(acc[mt][nt][1] + bz);
                        const float n = tanhf(o0 + bn + r * o1);
                        out[(size_t)rA * DD + f] = (1.f - z) * n + z * m;
                    } else {
                        out[(size_t)rA * DD + f] = m;
                    }
                }
                if (rB < N) {
                    const float m = __ldg(&mem[(size_t)rB * DD + f]);
                    if (g_counts[rB] > 0) {
                        const float r = sigmoidf_(acc[mt][nt][2] + br);
                        const float z = sigmoidf_(acc[mt][nt][3] + bz);
                        const float n = tanhf(o2 + bn + r * o3);
                        out[(size_t)rB * DD + f] = (1.f - z) * n + z * m;
                    } else {
                        out[(size_t)rB * DD + f] = m;
                    }
                }
            }
        }
    }
}

// ---------------------------------------------------------------------------
// Launch
// ---------------------------------------------------------------------------
extern "C" void kernel_launch(void* const* d_in, const int* in_sizes, int n_in,
                              void* d_out, int out_size)
{
    const float* s_raw  = (const float*)d_in[0];
    const float* d_raw  = (const float*)d_in[1];
    const int*   s_src  = (const int*)  d_in[2];
    const int*   d_src  = (const int*)  d_in[3];
    // d_in[4], d_in[5] = s_t, d_t : dead in the reference output, skipped
    const float* W_src  = (const float*)d_in[6];
    const float* b_src  = (const float*)d_in[7];
    const float* W_dst  = (const float*)d_in[8];
    const float* b_dst  = (const float*)d_in[9];
    const float* W_gru  = (const float*)d_in[10];
    const float* U_gru  = (const float*)d_in[11];
    const float* b_gru  = (const float*)d_in[12];
    const float* memory = (const float*)d_in[13];

    const int M = in_sizes[2];            // 200000 edges per store
    const int N = in_sizes[13] / DD;      // 100000 nodes
    float* out = (float*)d_out;
    const int n4 = N * (DD / 4);

    // K0: zero g_agg + counts
    zero_kernel<<<cdiv(n4, 256), 256>>>(n4, N);
    // K2: pack + tf32-round weights (gate matrix and both message W's)
    pack_kernel<<<cdiv(GK * G_LD, 256), 256>>>(W_gru, U_gru);
    pack_w_kernel<<<cdiv(2 * RAW_K * DD, 256), 256>>>(W_src, W_dst);
    // K1: counts
    count_kernel<<<cdiv(2 * M, 256), 256>>>(s_src, d_src, M);
    // K3: message GEMMs with fused scatter into g_agg
    {
        dim3 grid(cdiv(M, BM), DD / BN);
        msg_gemm_tc<<<grid, 256>>>(s_raw, 0, b_src, s_src, M);
        msg_gemm_tc<<<grid, 256>>>(d_raw, 1, b_dst, d_src, M);
    }
    // K4: gate GEMM + fully fused GRU epilogue -> final new_memory in d_out
    {
        dim3 grid(cdiv(N, BM), G_LD / BN);
        gru_gemm_tc<<<grid, 256>>>(memory, b_gru, out, N);
    }
}